// round 15
// baseline (speedup 1.0000x reference)
#include <cuda_runtime.h>
#include <cuda_bf16.h>

#define N_NODES 100000
#define N_EDGES 6400000
#define E_QUART (N_EDGES / 4)      // 1,600,000

// ---------------- scratch (allocation-free __device__ globals) ----------------
__device__ int    g_deg [N_NODES];
__device__ float  g_dinv[N_NODES];
__device__ float4 g_f4  [N_NODES];   // pre-scaled per-node features (width 4)
__device__ float4 g_c4  [N_NODES];   // scatter accumulator (width 4)
__device__ float2 g_f2  [N_NODES];   // width-2 (layer 3)
__device__ float2 g_c2  [N_NODES];

// ---------------- vector reductions (addresses clamped in-bounds) ------------
__device__ __forceinline__ void red_add_v4(float4* addr, float4 v) {
    asm volatile("red.global.add.v4.f32 [%0], {%1,%2,%3,%4};"
                 :: "l"(addr), "f"(v.x), "f"(v.y), "f"(v.z), "f"(v.w) : "memory");
}
__device__ __forceinline__ void red_add_v2(float2* addr, float2 v) {
    asm volatile("red.global.add.v2.f32 [%0], {%1,%2};"
                 :: "l"(addr), "f"(v.x), "f"(v.y) : "memory");
}

__device__ __forceinline__ int clampN(int v) {
    return min(max(v, 0), N_NODES - 1);
}

// ---------------- degree count (g_deg zeroed by memset) ----------------------
__global__ void k_deg_count(const int* __restrict__ dst) {
    int e = blockIdx.x * blockDim.x + threadIdx.x;
    if (e < N_EDGES) atomicAdd(&g_deg[clampN(dst[e])], 1);
}

// ---------------- layer 1: f4 = (x @ W1) * dinv ; c4 = f4 ; computes dinv ------
// block = 256 thr = 8 warps = 8 nodes; one coalesced LDG.128 per thread.
__global__ void k_mm1(const float* __restrict__ x, const float* __restrict__ W1) {
    __shared__ float4 sW[128];                   // W1 rows (128x4)
    __shared__ float  sx[8][128];                // 8 node rows
    int t = threadIdx.x;
    if (t < 128) sW[t] = ((const float4*)W1)[t];

    int base = blockIdx.x * 8;                   // 12500 * 8 == 100000 exactly
    float4 v = ((const float4*)(x + (size_t)base * 128))[t];
    ((float4*)sx)[t] = v;
    __syncthreads();

    int warp = t >> 5;
    int lane = t & 31;
    int n = base + warp;

    float p0 = 0.f, p1 = 0.f, p2 = 0.f, p3 = 0.f;
#pragma unroll
    for (int i = 0; i < 4; i++) {
        int k = lane + 32 * i;
        float xv = sx[warp][k];
        float4 w = sW[k];
        p0 += xv * w.x; p1 += xv * w.y; p2 += xv * w.z; p3 += xv * w.w;
    }
#pragma unroll
    for (int off = 16; off > 0; off >>= 1) {
        p0 += __shfl_down_sync(0xFFFFFFFFu, p0, off);
        p1 += __shfl_down_sync(0xFFFFFFFFu, p1, off);
        p2 += __shfl_down_sync(0xFFFFFFFFu, p2, off);
        p3 += __shfl_down_sync(0xFFFFFFFFu, p3, off);
    }
    if (lane == 0) {
        float di = rsqrtf((float)(g_deg[n] + 1));   // +1 self-loop
        g_dinv[n] = di;
        float4 g = make_float4(p0 * di, p1 * di, p2 * di, p3 * di);
        g_f4[n] = g;
        g_c4[n] = g;                             // self-loop contribution
    }
}

// ---------------- edge scatter, width 4: 4 edges/thread, loads before REDs ----
__global__ void k_edge4(const int* __restrict__ src, const int* __restrict__ dst) {
    int i = blockIdx.x * blockDim.x + threadIdx.x;
    if (i >= E_QUART) return;
    int e0 = i;
    int e1 = i + E_QUART;
    int e2 = i + 2 * E_QUART;
    int e3 = i + 3 * E_QUART;
    int s0 = clampN(src[e0]), d0 = clampN(dst[e0]);
    int s1 = clampN(src[e1]), d1 = clampN(dst[e1]);
    int s2 = clampN(src[e2]), d2 = clampN(dst[e2]);
    int s3 = clampN(src[e3]), d3 = clampN(dst[e3]);
    float4 v0 = g_f4[s0];
    float4 v1 = g_f4[s1];
    float4 v2 = g_f4[s2];
    float4 v3 = g_f4[s3];
    red_add_v4(&g_c4[d0], v0);
    red_add_v4(&g_c4[d1], v1);
    red_add_v4(&g_c4[d2], v2);
    red_add_v4(&g_c4[d3], v3);
}

// ---------------- finalize L1 + matmul L2 (4x4) ----------------
__global__ void k_f1mm2(const float* __restrict__ b1, const float* __restrict__ W2) {
    int n = blockIdx.x * blockDim.x + threadIdx.x;
    if (n >= N_NODES) return;
    float di = g_dinv[n];
    float4 a = g_c4[n];
    float h0 = tanhf(di * a.x + b1[0]);
    float h1 = tanhf(di * a.y + b1[1]);
    float h2 = tanhf(di * a.z + b1[2]);
    float h3 = tanhf(di * a.w + b1[3]);
    float4 g;
    g.x = (h0 * W2[0] + h1 * W2[4] + h2 * W2[8]  + h3 * W2[12]) * di;
    g.y = (h0 * W2[1] + h1 * W2[5] + h2 * W2[9]  + h3 * W2[13]) * di;
    g.z = (h0 * W2[2] + h1 * W2[6] + h2 * W2[10] + h3 * W2[14]) * di;
    g.w = (h0 * W2[3] + h1 * W2[7] + h2 * W2[11] + h3 * W2[15]) * di;
    g_f4[n] = g;
    g_c4[n] = g;                                 // self-loop
}

// ---------------- finalize L2 + matmul L3 (4x2) ----------------
__global__ void k_f2mm3(const float* __restrict__ b2, const float* __restrict__ W3) {
    int n = blockIdx.x * blockDim.x + threadIdx.x;
    if (n >= N_NODES) return;
    float di = g_dinv[n];
    float4 a = g_c4[n];
    float h0 = tanhf(di * a.x + b2[0]);
    float h1 = tanhf(di * a.y + b2[1]);
    float h2 = tanhf(di * a.z + b2[2]);
    float h3 = tanhf(di * a.w + b2[3]);
    float2 g;
    g.x = (h0 * W3[0] + h1 * W3[2] + h2 * W3[4] + h3 * W3[6]) * di;
    g.y = (h0 * W3[1] + h1 * W3[3] + h2 * W3[5] + h3 * W3[7]) * di;
    g_f2[n] = g;
    g_c2[n] = g;                                 // self-loop
}

// ---------------- edge scatter, width 2: 4 edges/thread ----------------
__global__ void k_edge2(const int* __restrict__ src, const int* __restrict__ dst) {
    int i = blockIdx.x * blockDim.x + threadIdx.x;
    if (i >= E_QUART) return;
    int e0 = i;
    int e1 = i + E_QUART;
    int e2 = i + 2 * E_QUART;
    int e3 = i + 3 * E_QUART;
    int s0 = clampN(src[e0]), d0 = clampN(dst[e0]);
    int s1 = clampN(src[e1]), d1 = clampN(dst[e1]);
    int s2 = clampN(src[e2]), d2 = clampN(dst[e2]);
    int s3 = clampN(src[e3]), d3 = clampN(dst[e3]);
    float2 v0 = g_f2[s0];
    float2 v1 = g_f2[s1];
    float2 v2 = g_f2[s2];
    float2 v3 = g_f2[s3];
    red_add_v2(&g_c2[d0], v0);
    red_add_v2(&g_c2[d1], v1);
    red_add_v2(&g_c2[d2], v2);
    red_add_v2(&g_c2[d3], v3);
}

// ---------------- finalize L3 + classifier ----------------
__global__ void k_final(const float* __restrict__ b3,
                        const float* __restrict__ Wc, const float* __restrict__ bc,
                        float* __restrict__ out, float* __restrict__ hout) {
    int n = blockIdx.x * blockDim.x + threadIdx.x;
    if (n >= N_NODES) return;
    float di = g_dinv[n];
    float2 a = g_c2[n];
    float h0 = tanhf(di * a.x + b3[0]);
    float h1 = tanhf(di * a.y + b3[1]);
    float* o = out + (size_t)n * 10;
#pragma unroll
    for (int j = 0; j < 10; j++)
        o[j] = h0 * Wc[j] + h1 * Wc[10 + j] + bc[j];
    hout[2 * n + 0] = h0;
    hout[2 * n + 1] = h1;
}

// ---------------- launch ----------------
extern "C" void kernel_launch(void* const* d_in, const int* in_sizes, int n_in,
                              void* d_out, int out_size) {
    const float* x  = (const float*)d_in[0];
    const int*   ei = (const int*)d_in[1];        // int32, [2, E] row-major
    const float* W1 = (const float*)d_in[2];
    const float* b1 = (const float*)d_in[3];
    const float* W2 = (const float*)d_in[4];
    const float* b2 = (const float*)d_in[5];
    const float* W3 = (const float*)d_in[6];
    const float* b3 = (const float*)d_in[7];
    const float* Wc = (const float*)d_in[8];
    const float* bc = (const float*)d_in[9];

    const int* src = ei;            // row 0
    const int* dst = ei + N_EDGES;  // row 1

    float* out  = (float*)d_out;                  // [N, 10]
    float* hout = out + (size_t)N_NODES * 10;     // [N, 2]

    // zero degree counters (graph-capturable, no allocation)
    void* degPtr = nullptr;
    cudaGetSymbolAddress(&degPtr, g_deg);
    cudaMemsetAsync(degPtr, 0, N_NODES * sizeof(int));

    const int T = 256;
    const int nodeBlocks  = (N_NODES + T - 1) / T;
    const int edgeBlocks  = (N_EDGES + T - 1) / T;
    const int quartBlocks = (E_QUART + T - 1) / T;        // 6250
    const int mm1Blocks   = N_NODES / 8;                  // 12500, exact

    k_deg_count<<<edgeBlocks, T>>>(dst);

    k_mm1      <<<mm1Blocks, T>>>(x, W1);
    k_edge4    <<<quartBlocks, T>>>(src, dst);

    k_f1mm2    <<<nodeBlocks, T>>>(b1, W2);
    k_edge4    <<<quartBlocks, T>>>(src, dst);

    k_f2mm3    <<<nodeBlocks, T>>>(b2, W3);
    k_edge2    <<<quartBlocks, T>>>(src, dst);

    k_final    <<<nodeBlocks, T>>>(b3, Wc, bc, out, hout);
}

// round 16
// speedup vs baseline: 1.4909x; 1.4909x over previous
#include <cuda_runtime.h>
#include <cuda_bf16.h>

#define N_NODES 100000
#define N_EDGES 6400000
#define E_HALF  (N_EDGES / 2)

// ---------------- scratch (allocation-free __device__ globals) ----------------
__device__ int    g_deg [N_NODES];
__device__ float  g_dinv[N_NODES];
__device__ float4 g_f4  [N_NODES];   // pre-scaled per-node features (width 4)
__device__ float4 g_c4  [N_NODES];   // scatter accumulator (width 4)
__device__ float2 g_f2  [N_NODES];   // width-2 (layer 3)
__device__ float2 g_c2  [N_NODES];

// ---------------- vector reductions (addresses clamped in-bounds) ------------
__device__ __forceinline__ void red_add_v4(float4* addr, float4 v) {
    asm volatile("red.global.add.v4.f32 [%0], {%1,%2,%3,%4};"
                 :: "l"(addr), "f"(v.x), "f"(v.y), "f"(v.z), "f"(v.w) : "memory");
}
__device__ __forceinline__ void red_add_v2(float2* addr, float2 v) {
    asm volatile("red.global.add.v2.f32 [%0], {%1,%2};"
                 :: "l"(addr), "f"(v.x), "f"(v.y) : "memory");
}

__device__ __forceinline__ int clampN(int v) {
    return min(max(v, 0), N_NODES - 1);
}

// ---------------- degree count (g_deg zeroed by memset; +1 self-loop in dinv) --
__global__ void k_deg_count(const int* __restrict__ dst) {
    int e = blockIdx.x * blockDim.x + threadIdx.x;
    if (e < N_EDGES) atomicAdd(&g_deg[clampN(dst[e])], 1);
}

// ---------------- layer 1: f4 = (x @ W1) * dinv ; c4 = f4 ; computes dinv ------
// block = 256 thr = 8 warps = 8 nodes. 8 rows = 1024 contiguous floats =
// 256 float4 -> one coalesced LDG.128 per thread into smem (conflict-free),
// then warp-per-node scalar smem reads (k = lane+32*i, conflict-free).
__global__ void k_mm1(const float* __restrict__ x, const float* __restrict__ W1) {
    __shared__ float4 sW[128];                   // W1 rows (128x4)
    __shared__ float  sx[8][128];                // 8 node rows
    int t = threadIdx.x;
    if (t < 128) sW[t] = ((const float4*)W1)[t];

    int base = blockIdx.x * 8;                   // 12500 * 8 == 100000 exactly
    float4 v = ((const float4*)(x + (size_t)base * 128))[t];
    ((float4*)sx)[t] = v;
    __syncthreads();

    int warp = t >> 5;
    int lane = t & 31;
    int n = base + warp;

    float p0 = 0.f, p1 = 0.f, p2 = 0.f, p3 = 0.f;
#pragma unroll
    for (int i = 0; i < 4; i++) {
        int k = lane + 32 * i;
        float xv = sx[warp][k];
        float4 w = sW[k];
        p0 += xv * w.x; p1 += xv * w.y; p2 += xv * w.z; p3 += xv * w.w;
    }
#pragma unroll
    for (int off = 16; off > 0; off >>= 1) {
        p0 += __shfl_down_sync(0xFFFFFFFFu, p0, off);
        p1 += __shfl_down_sync(0xFFFFFFFFu, p1, off);
        p2 += __shfl_down_sync(0xFFFFFFFFu, p2, off);
        p3 += __shfl_down_sync(0xFFFFFFFFu, p3, off);
    }
    if (lane == 0) {
        float di = rsqrtf((float)(g_deg[n] + 1));   // +1 self-loop
        g_dinv[n] = di;
        float4 g = make_float4(p0 * di, p1 * di, p2 * di, p3 * di);
        g_f4[n] = g;
        g_c4[n] = g;                             // self-loop contribution
    }
}

// ---------------- edge scatter, width 4: 2 edges/thread for MLP ---------------
__global__ void k_edge4(const int* __restrict__ src, const int* __restrict__ dst) {
    int i = blockIdx.x * blockDim.x + threadIdx.x;
    if (i >= E_HALF) return;
    int e0 = i, e1 = i + E_HALF;
    int s0 = clampN(src[e0]);
    int d0 = clampN(dst[e0]);
    int s1 = clampN(src[e1]);
    int d1 = clampN(dst[e1]);
    float4 v0 = g_f4[s0];
    float4 v1 = g_f4[s1];
    red_add_v4(&g_c4[d0], v0);
    red_add_v4(&g_c4[d1], v1);
}

// ---------------- finalize L1 + matmul L2 (4x4) ----------------
__global__ void k_f1mm2(const float* __restrict__ b1, const float* __restrict__ W2) {
    int n = blockIdx.x * blockDim.x + threadIdx.x;
    if (n >= N_NODES) return;
    float di = g_dinv[n];
    float4 a = g_c4[n];
    float h0 = tanhf(di * a.x + b1[0]);
    float h1 = tanhf(di * a.y + b1[1]);
    float h2 = tanhf(di * a.z + b1[2]);
    float h3 = tanhf(di * a.w + b1[3]);
    float4 g;
    g.x = (h0 * W2[0] + h1 * W2[4] + h2 * W2[8]  + h3 * W2[12]) * di;
    g.y = (h0 * W2[1] + h1 * W2[5] + h2 * W2[9]  + h3 * W2[13]) * di;
    g.z = (h0 * W2[2] + h1 * W2[6] + h2 * W2[10] + h3 * W2[14]) * di;
    g.w = (h0 * W2[3] + h1 * W2[7] + h2 * W2[11] + h3 * W2[15]) * di;
    g_f4[n] = g;
    g_c4[n] = g;                                 // self-loop
}

// ---------------- finalize L2 + matmul L3 (4x2) ----------------
__global__ void k_f2mm3(const float* __restrict__ b2, const float* __restrict__ W3) {
    int n = blockIdx.x * blockDim.x + threadIdx.x;
    if (n >= N_NODES) return;
    float di = g_dinv[n];
    float4 a = g_c4[n];
    float h0 = tanhf(di * a.x + b2[0]);
    float h1 = tanhf(di * a.y + b2[1]);
    float h2 = tanhf(di * a.z + b2[2]);
    float h3 = tanhf(di * a.w + b2[3]);
    float2 g;
    g.x = (h0 * W3[0] + h1 * W3[2] + h2 * W3[4] + h3 * W3[6]) * di;
    g.y = (h0 * W3[1] + h1 * W3[3] + h2 * W3[5] + h3 * W3[7]) * di;
    g_f2[n] = g;
    g_c2[n] = g;                                 // self-loop
}

// ---------------- edge scatter, width 2: 2 edges/thread ----------------
__global__ void k_edge2(const int* __restrict__ src, const int* __restrict__ dst) {
    int i = blockIdx.x * blockDim.x + threadIdx.x;
    if (i >= E_HALF) return;
    int e0 = i, e1 = i + E_HALF;
    int s0 = clampN(src[e0]);
    int d0 = clampN(dst[e0]);
    int s1 = clampN(src[e1]);
    int d1 = clampN(dst[e1]);
    float2 v0 = g_f2[s0];
    float2 v1 = g_f2[s1];
    red_add_v2(&g_c2[d0], v0);
    red_add_v2(&g_c2[d1], v1);
}

// ---------------- finalize L3 + classifier ----------------
__global__ void k_final(const float* __restrict__ b3,
                        const float* __restrict__ Wc, const float* __restrict__ bc,
                        float* __restrict__ out, float* __restrict__ hout) {
    int n = blockIdx.x * blockDim.x + threadIdx.x;
    if (n >= N_NODES) return;
    float di = g_dinv[n];
    float2 a = g_c2[n];
    float h0 = tanhf(di * a.x + b3[0]);
    float h1 = tanhf(di * a.y + b3[1]);
    float* o = out + (size_t)n * 10;
#pragma unroll
    for (int j = 0; j < 10; j++)
        o[j] = h0 * Wc[j] + h1 * Wc[10 + j] + bc[j];
    hout[2 * n + 0] = h0;
    hout[2 * n + 1] = h1;
}

// ---------------- launch ----------------
extern "C" void kernel_launch(void* const* d_in, const int* in_sizes, int n_in,
                              void* d_out, int out_size) {
    const float* x  = (const float*)d_in[0];
    const int*   ei = (const int*)d_in[1];        // int32, [2, E] row-major
    const float* W1 = (const float*)d_in[2];
    const float* b1 = (const float*)d_in[3];
    const float* W2 = (const float*)d_in[4];
    const float* b2 = (const float*)d_in[5];
    const float* W3 = (const float*)d_in[6];
    const float* b3 = (const float*)d_in[7];
    const float* Wc = (const float*)d_in[8];
    const float* bc = (const float*)d_in[9];

    const int* src = ei;            // row 0
    const int* dst = ei + N_EDGES;  // row 1

    float* out  = (float*)d_out;                  // [N, 10]
    float* hout = out + (size_t)N_NODES * 10;     // [N, 2]

    // zero degree counters (graph-capturable, no allocation)
    void* degPtr = nullptr;
    cudaGetSymbolAddress(&degPtr, g_deg);
    cudaMemsetAsync(degPtr, 0, N_NODES * sizeof(int));

    const int T = 256;
    const int nodeBlocks  = (N_NODES + T - 1) / T;
    const int edgeBlocks  = (N_EDGES + T - 1) / T;
    const int halfBlocks  = (E_HALF + T - 1) / T;
    const int mm1Blocks   = N_NODES / 8;          // 12500, exact

    k_deg_count<<<edgeBlocks, T>>>(dst);

    k_mm1      <<<mm1Blocks, T>>>(x, W1);
    k_edge4    <<<halfBlocks, T>>>(src, dst);

    k_f1mm2    <<<nodeBlocks, T>>>(b1, W2);
    k_edge4    <<<halfBlocks, T>>>(src, dst);

    k_f2mm3    <<<nodeBlocks, T>>>(b2, W3);
    k_edge2    <<<halfBlocks, T>>>(src, dst);

    k_final    <<<nodeBlocks, T>>>(b3, Wc, bc, out, hout);
}

// round 17
// speedup vs baseline: 1.6205x; 1.0869x over previous
#include <cuda_runtime.h>
#include <cuda_bf16.h>

#define N_NODES 100000
#define N_EDGES 6400000
#define E_HALF  (N_EDGES / 2)
#define FUSE_BLOCKS 37500        // 12500 mm (bid%3==0) + 25000 deg (others)

// ---------------- scratch (allocation-free __device__ globals) ----------------
__device__ int    g_deg [N_NODES];
__device__ float  g_dinv[N_NODES];
__device__ float4 g_p4  [N_NODES];   // raw x@W1 (pre-dinv)
__device__ float4 g_f4  [N_NODES];   // pre-scaled per-node features (width 4)
__device__ float4 g_c4  [N_NODES];   // scatter accumulator (width 4)
__device__ float2 g_f2  [N_NODES];   // width-2 (layer 3)
__device__ float2 g_c2  [N_NODES];

// ---------------- vector reductions (addresses clamped in-bounds) ------------
__device__ __forceinline__ void red_add_v4(float4* addr, float4 v) {
    asm volatile("red.global.add.v4.f32 [%0], {%1,%2,%3,%4};"
                 :: "l"(addr), "f"(v.x), "f"(v.y), "f"(v.z), "f"(v.w) : "memory");
}
__device__ __forceinline__ void red_add_v2(float2* addr, float2 v) {
    asm volatile("red.global.add.v2.f32 [%0], {%1,%2};"
                 :: "l"(addr), "f"(v.x), "f"(v.y) : "memory");
}

__device__ __forceinline__ int clampN(int v) {
    return min(max(v, 0), N_NODES - 1);
}

// ---------------- fused deg ∥ raw-mm1, modulo-interleaved ---------------------
// bid % 3 == 0 -> mm job (8 nodes/block); else -> degree-count job.
// Every scheduling wave carries a 1:2 mm:deg mix, so DRAM streaming overlaps
// LTS atomics for the entire launch (fixes R13's front-loaded ordering).
__global__ void k_fused(const float* __restrict__ x, const float* __restrict__ W1,
                        const int* __restrict__ dst) {
    int bid = blockIdx.x;
    if (bid % 3 != 0) {
        // ---- degree-count job: deg block index db in [0, 25000) ----
        int db = bid - bid / 3 - 1;
        int e = db * 256 + threadIdx.x;          // e < 6,400,000 exactly
        atomicAdd(&g_deg[clampN(dst[e])], 1);
        return;
    }
    // ---- raw mm1 job: mm block index mb in [0, 12500) ----
    int mb = bid / 3;
    __shared__ float4 sW[128];                   // W1 rows (128x4)
    __shared__ float  sx[8][128];                // 8 node rows
    int t = threadIdx.x;
    if (t < 128) sW[t] = ((const float4*)W1)[t];

    int base = mb * 8;                           // 12500 * 8 == 100000 exactly
    float4 v = ((const float4*)(x + (size_t)base * 128))[t];
    ((float4*)sx)[t] = v;
    __syncthreads();

    int warp = t >> 5;
    int lane = t & 31;

    float p0 = 0.f, p1 = 0.f, p2 = 0.f, p3 = 0.f;
#pragma unroll
    for (int i = 0; i < 4; i++) {
        int k = lane + 32 * i;
        float xv = sx[warp][k];
        float4 w = sW[k];
        p0 += xv * w.x; p1 += xv * w.y; p2 += xv * w.z; p3 += xv * w.w;
    }
#pragma unroll
    for (int off = 16; off > 0; off >>= 1) {
        p0 += __shfl_down_sync(0xFFFFFFFFu, p0, off);
        p1 += __shfl_down_sync(0xFFFFFFFFu, p1, off);
        p2 += __shfl_down_sync(0xFFFFFFFFu, p2, off);
        p3 += __shfl_down_sync(0xFFFFFFFFu, p3, off);
    }
    if (lane == 0)
        g_p4[base + warp] = make_float4(p0, p1, p2, p3);
}

// ---------------- scale: dinv = rsqrt(deg+1); f4 = c4 = p4 * dinv --------------
__global__ void k_scale() {
    int n = blockIdx.x * blockDim.x + threadIdx.x;
    if (n >= N_NODES) return;
    float di = rsqrtf((float)(g_deg[n] + 1));    // +1 self-loop
    g_dinv[n] = di;
    float4 p = g_p4[n];
    float4 g = make_float4(p.x * di, p.y * di, p.z * di, p.w * di);
    g_f4[n] = g;
    g_c4[n] = g;                                 // self-loop contribution
}

// ---------------- edge scatter, width 4: 2 edges/thread (proven optimum) ------
__global__ void k_edge4(const int* __restrict__ src, const int* __restrict__ dst) {
    int i = blockIdx.x * blockDim.x + threadIdx.x;
    if (i >= E_HALF) return;
    int e0 = i, e1 = i + E_HALF;
    int s0 = clampN(src[e0]);
    int d0 = clampN(dst[e0]);
    int s1 = clampN(src[e1]);
    int d1 = clampN(dst[e1]);
    float4 v0 = g_f4[s0];
    float4 v1 = g_f4[s1];
    red_add_v4(&g_c4[d0], v0);
    red_add_v4(&g_c4[d1], v1);
}

// ---------------- finalize L1 + matmul L2 (4x4) ----------------
__global__ void k_f1mm2(const float* __restrict__ b1, const float* __restrict__ W2) {
    int n = blockIdx.x * blockDim.x + threadIdx.x;
    if (n >= N_NODES) return;
    float di = g_dinv[n];
    float4 a = g_c4[n];
    float h0 = tanhf(di * a.x + b1[0]);
    float h1 = tanhf(di * a.y + b1[1]);
    float h2 = tanhf(di * a.z + b1[2]);
    float h3 = tanhf(di * a.w + b1[3]);
    float4 g;
    g.x = (h0 * W2[0] + h1 * W2[4] + h2 * W2[8]  + h3 * W2[12]) * di;
    g.y = (h0 * W2[1] + h1 * W2[5] + h2 * W2[9]  + h3 * W2[13]) * di;
    g.z = (h0 * W2[2] + h1 * W2[6] + h2 * W2[10] + h3 * W2[14]) * di;
    g.w = (h0 * W2[3] + h1 * W2[7] + h2 * W2[11] + h3 * W2[15]) * di;
    g_f4[n] = g;
    g_c4[n] = g;                                 // self-loop
}

// ---------------- finalize L2 + matmul L3 (4x2) ----------------
__global__ void k_f2mm3(const float* __restrict__ b2, const float* __restrict__ W3) {
    int n = blockIdx.x * blockDim.x + threadIdx.x;
    if (n >= N_NODES) return;
    float di = g_dinv[n];
    float4 a = g_c4[n];
    float h0 = tanhf(di * a.x + b2[0]);
    float h1 = tanhf(di * a.y + b2[1]);
    float h2 = tanhf(di * a.z + b2[2]);
    float h3 = tanhf(di * a.w + b2[3]);
    float2 g;
    g.x = (h0 * W3[0] + h1 * W3[2] + h2 * W3[4] + h3 * W3[6]) * di;
    g.y = (h0 * W3[1] + h1 * W3[3] + h2 * W3[5] + h3 * W3[7]) * di;
    g_f2[n] = g;
    g_c2[n] = g;                                 // self-loop
}

// ---------------- edge scatter, width 2: 2 edges/thread ----------------
__global__ void k_edge2(const int* __restrict__ src, const int* __restrict__ dst) {
    int i = blockIdx.x * blockDim.x + threadIdx.x;
    if (i >= E_HALF) return;
    int e0 = i, e1 = i + E_HALF;
    int s0 = clampN(src[e0]);
    int d0 = clampN(dst[e0]);
    int s1 = clampN(src[e1]);
    int d1 = clampN(dst[e1]);
    float2 v0 = g_f2[s0];
    float2 v1 = g_f2[s1];
    red_add_v2(&g_c2[d0], v0);
    red_add_v2(&g_c2[d1], v1);
}

// ---------------- finalize L3 + classifier ----------------
__global__ void k_final(const float* __restrict__ b3,
                        const float* __restrict__ Wc, const float* __restrict__ bc,
                        float* __restrict__ out, float* __restrict__ hout) {
    int n = blockIdx.x * blockDim.x + threadIdx.x;
    if (n >= N_NODES) return;
    float di = g_dinv[n];
    float2 a = g_c2[n];
    float h0 = tanhf(di * a.x + b3[0]);
    float h1 = tanhf(di * a.y + b3[1]);
    float* o = out + (size_t)n * 10;
#pragma unroll
    for (int j = 0; j < 10; j++)
        o[j] = h0 * Wc[j] + h1 * Wc[10 + j] + bc[j];
    hout[2 * n + 0] = h0;
    hout[2 * n + 1] = h1;
}

// ---------------- launch ----------------
extern "C" void kernel_launch(void* const* d_in, const int* in_sizes, int n_in,
                              void* d_out, int out_size) {
    const float* x  = (const float*)d_in[0];
    const int*   ei = (const int*)d_in[1];        // int32, [2, E] row-major
    const float* W1 = (const float*)d_in[2];
    const float* b1 = (const float*)d_in[3];
    const float* W2 = (const float*)d_in[4];
    const float* b2 = (const float*)d_in[5];
    const float* W3 = (const float*)d_in[6];
    const float* b3 = (const float*)d_in[7];
    const float* Wc = (const float*)d_in[8];
    const float* bc = (const float*)d_in[9];

    const int* src = ei;            // row 0
    const int* dst = ei + N_EDGES;  // row 1

    float* out  = (float*)d_out;                  // [N, 10]
    float* hout = out + (size_t)N_NODES * 10;     // [N, 2]

    // zero degree counters (graph-capturable, no allocation)
    void* degPtr = nullptr;
    cudaGetSymbolAddress(&degPtr, g_deg);
    cudaMemsetAsync(degPtr, 0, N_NODES * sizeof(int));

    const int T = 256;
    const int nodeBlocks = (N_NODES + T - 1) / T;
    const int halfBlocks = (E_HALF + T - 1) / T;

    k_fused <<<FUSE_BLOCKS, T>>>(x, W1, dst);     // deg ∥ raw-mm1, interleaved
    k_scale <<<nodeBlocks, T>>>();

    k_edge4 <<<halfBlocks, T>>>(src, dst);
    k_f1mm2 <<<nodeBlocks, T>>>(b1, W2);

    k_edge4 <<<halfBlocks, T>>>(src, dst);
    k_f2mm3 <<<nodeBlocks, T>>>(b2, W3);

    k_edge2 <<<halfBlocks, T>>>(src, dst);
    k_final <<<nodeBlocks, T>>>(b3, Wc, bc, out, hout);
}